// round 2
// baseline (speedup 1.0000x reference)
#include <cuda_runtime.h>
#include <math.h>

#define T 2048
#define HID 1280
#define NH 16
#define HD 80
#define THID (3*HID)

// Scratch (no allocation allowed in kernel_launch)
__device__ float g_qkv[T*THID];     // qkv = x@Wqkv + b     (2048 x 3840)
__device__ float g_q[NH*T*HD];      // roped Q  [head][T][80]
__device__ float g_k[NH*T*HD];      // roped K  [head][T][80]
__device__ float g_v[NH*T*HD];      // V        [head][T][80]
__device__ float g_att[T*HID];      // attention output [T][1280]

// ---------------------------------------------------------------------------
// Tiled fp32 GEMM: C[M,N] = A[M,K] @ B[K,N] + bias[N]
// 64x64 block tile, 16-wide K tile, 4x4 register micro-tile, 256 threads.
// ---------------------------------------------------------------------------
__global__ void gemm_bias_kernel(const float* __restrict__ A,
                                 const float* __restrict__ B,
                                 const float* __restrict__ bias,
                                 float* __restrict__ C,
                                 int M, int N, int K)
{
    __shared__ float Ast[16][64];   // A tile stored transposed [k][m]
    __shared__ float Bs[16][64];    // B tile [k][n]
    const int tid = threadIdx.x;
    const int tx = tid & 15, ty = tid >> 4;
    const int m0 = blockIdx.y * 64, n0 = blockIdx.x * 64;

    float acc[4][4] = {};

    const int a_row = tid >> 2;            // 0..63
    const int a_col = (tid & 3) * 4;       // 0,4,8,12
    const int b_row = tid >> 4;            // 0..15
    const int b_col = (tid & 15) * 4;      // 0..60
    const float* Aptr = A + (size_t)(m0 + a_row) * K + a_col;
    const float* Bptr = B + (size_t)b_row * N + n0 + b_col;

    for (int k0 = 0; k0 < K; k0 += 16) {
        float4 av = *(const float4*)(Aptr + k0);
        float4 bv = *(const float4*)(Bptr + (size_t)k0 * N);
        Ast[a_col + 0][a_row] = av.x;
        Ast[a_col + 1][a_row] = av.y;
        Ast[a_col + 2][a_row] = av.z;
        Ast[a_col + 3][a_row] = av.w;
        *(float4*)&Bs[b_row][b_col] = bv;
        __syncthreads();
        #pragma unroll
        for (int kk = 0; kk < 16; kk++) {
            float4 a4 = *(const float4*)&Ast[kk][ty * 4];
            float4 b4 = *(const float4*)&Bs[kk][tx * 4];
            float ar[4] = {a4.x, a4.y, a4.z, a4.w};
            float br[4] = {b4.x, b4.y, b4.z, b4.w};
            #pragma unroll
            for (int i = 0; i < 4; i++)
                #pragma unroll
                for (int j = 0; j < 4; j++)
                    acc[i][j] += ar[i] * br[j];
        }
        __syncthreads();
    }

    #pragma unroll
    for (int i = 0; i < 4; i++) {
        int row = m0 + ty * 4 + i;
        #pragma unroll
        for (int j = 0; j < 4; j++) {
            int col = n0 + tx * 4 + j;
            C[(size_t)row * N + col] = acc[i][j] + bias[col];
        }
    }
}

// ---------------------------------------------------------------------------
// RoPE + split qkv into per-head [head][T][80] buffers.
// ---------------------------------------------------------------------------
__global__ void rope_split_kernel(const float* __restrict__ rope)
{
    int idx = blockIdx.x * blockDim.x + threadIdx.x;
    if (idx >= T * NH * HD) return;
    int d = idx % HD;
    int n = (idx / HD) % NH;
    int t = idx / (HD * NH);

    int dr = (d < 40) ? d : d - 40;
    float ang = rope[t * 40 + dr];
    float c = cosf(ang), s = sinf(ang);

    const float* qrow = g_qkv + (size_t)t * THID + n * HD;
    float qv, kv;
    if (d < 40) {
        qv = qrow[d] * c        - qrow[d + 40] * s;
        kv = qrow[HID + d] * c  - qrow[HID + d + 40] * s;
    } else {
        qv = qrow[d - 40] * s       + qrow[d] * c;
        kv = qrow[HID + d - 40] * s + qrow[HID + d] * c;
    }
    int o = (n * T + t) * HD + d;
    g_q[o] = qv;
    g_k[o] = kv;
    g_v[o] = qrow[2 * HID + d];
}

// ---------------------------------------------------------------------------
// Flash attention with block-diagonal masking (segment_ids sorted).
// Block = 64 query rows of one head. 256 threads: 4 lanes per row.
// Lane `sub` computes scores for keys {jj*4+sub} and owns output dims
// [sub*20, sub*20+20). PV cross-combines all 32 keys per block via width-4
// shfl broadcast of the probabilities.
// ---------------------------------------------------------------------------
__global__ void attn_kernel(const int* __restrict__ seg)
{
    const int n = blockIdx.y;
    const int q0 = blockIdx.x * 64;
    const int tid = threadIdx.x;
    const int row = tid >> 2;      // 0..63
    const int sub = tid & 3;       // 0..3

    __shared__ float Qs[64 * HD];
    __shared__ float Ks[32 * HD];
    __shared__ float Vs[32 * HD];
    __shared__ int   segk[32];

    const float* qbase = g_q + (size_t)(n * T + q0) * HD;
    for (int i = tid; i < 64 * HD; i += 256) Qs[i] = qbase[i];

    const int myseg  = seg[q0 + row];
    const int seg_lo = seg[q0];
    const int seg_hi = seg[q0 + 63];

    int lo = 0, hi = T;
    while (lo < hi) { int mid = (lo + hi) >> 1; if (seg[mid] < seg_lo) lo = mid + 1; else hi = mid; }
    const int kstart = lo;
    hi = T;
    while (lo < hi) { int mid = (lo + hi) >> 1; if (seg[mid] <= seg_hi) lo = mid + 1; else hi = mid; }
    const int kend = lo;

    float m = -1e30f, l = 0.f;
    float accv[20];
    #pragma unroll
    for (int i = 0; i < 20; i++) accv[i] = 0.f;
    const float scale = 0.11180339887498949f;   // 1/sqrt(80)

    for (int kb = kstart & ~31; kb < kend; kb += 32) {
        __syncthreads();   // protect Ks/Vs from previous iteration (and Qs on iter 0)
        for (int i = tid; i < 32 * HD; i += 256) {
            int kk = i / HD, d = i % HD;
            int kg = kb + kk;
            float kvv = 0.f, vvv = 0.f;
            if (kg < kend) {
                kvv = g_k[(size_t)(n * T + kg) * HD + d];
                vvv = g_v[(size_t)(n * T + kg) * HD + d];
            }
            Ks[i] = kvv; Vs[i] = vvv;
        }
        if (tid < 32) segk[tid] = (kb + tid < T) ? seg[kb + tid] : -1;
        __syncthreads();

        // Scores: each lane handles 8 keys (k = kb + jj*4 + sub)
        float sc[8];
        unsigned vb = 0;
        #pragma unroll
        for (int jj = 0; jj < 8; jj++) {
            int kk = jj * 4 + sub;
            int kg = kb + kk;
            const float4* qr = (const float4*)(Qs + row * HD);
            const float4* kr = (const float4*)(Ks + kk * HD);
            float s = 0.f;
            #pragma unroll
            for (int d4 = 0; d4 < 20; d4++) {
                float4 a = qr[d4], b = kr[d4];
                s += a.x * b.x + a.y * b.y + a.z * b.z + a.w * b.w;
            }
            sc[jj] = s * scale;
            if (kg >= kstart && kg < kend && segk[kk] == myseg) vb |= (1u << jj);
        }

        // Online softmax: max over 8 local keys, then across the 4 lanes
        float cm = -1e30f;
        #pragma unroll
        for (int jj = 0; jj < 8; jj++) if (vb & (1u << jj)) cm = fmaxf(cm, sc[jj]);
        cm = fmaxf(cm, __shfl_xor_sync(0xffffffffu, cm, 1));
        cm = fmaxf(cm, __shfl_xor_sync(0xffffffffu, cm, 2));
        float mnew = fmaxf(m, cm);
        float factor = __expf(m - mnew);
        m = mnew;
        l *= factor;
        #pragma unroll
        for (int i = 0; i < 20; i++) accv[i] *= factor;

        float p[8];
        #pragma unroll
        for (int jj = 0; jj < 8; jj++) {
            p[jj] = (vb & (1u << jj)) ? __expf(sc[jj] - m) : 0.f;
            l += p[jj];
        }

        // PV: broadcast probabilities across the 4 cooperating lanes so that
        // ALL 32 keys contribute to this lane's 20 output dims.
        #pragma unroll
        for (int jj = 0; jj < 8; jj++) {
            #pragma unroll
            for (int src = 0; src < 4; src++) {
                float pj = __shfl_sync(0xffffffffu, p[jj], src, 4); // lane `src` of this 4-group
                int kk = jj * 4 + src;
                const float* vr = Vs + kk * HD + sub * 20;
                #pragma unroll
                for (int i = 0; i < 20; i++) accv[i] += pj * vr[i];
            }
        }
    }

    // Combine l across the 4 cooperating lanes (m already consistent)
    l += __shfl_xor_sync(0xffffffffu, l, 1);
    l += __shfl_xor_sync(0xffffffffu, l, 2);
    float inv = 1.f / l;

    float* o = g_att + (size_t)(q0 + row) * HID + n * HD + sub * 20;
    #pragma unroll
    for (int i = 0; i < 20; i++) o[i] = accv[i] * inv;
}

// ---------------------------------------------------------------------------
extern "C" void kernel_launch(void* const* d_in, const int* in_sizes, int n_in,
                              void* d_out, int out_size)
{
    const float* x     = (const float*)d_in[0];
    const float* rope  = (const float*)d_in[1];
    const int*   seg   = (const int*)  d_in[2];
    const float* qkvW  = (const float*)d_in[3];
    const float* qkvB  = (const float*)d_in[4];
    const float* projW = (const float*)d_in[5];
    const float* projB = (const float*)d_in[6];
    float* out = (float*)d_out;

    float *p_qkv, *p_att;
    cudaGetSymbolAddress((void**)&p_qkv, g_qkv);
    cudaGetSymbolAddress((void**)&p_att, g_att);

    // 1. qkv = x @ Wqkv + b        (2048 x 3840, K=1280)
    gemm_bias_kernel<<<dim3(THID / 64, T / 64), 256>>>(x, qkvW, qkvB, p_qkv, T, THID, HID);

    // 2. RoPE + split into per-head Q,K,V
    rope_split_kernel<<<(T * NH * HD + 255) / 256, 256>>>(rope);

    // 3. Block-diagonal flash attention
    attn_kernel<<<dim3(T / 64, NH), 256>>>(seg);

    // 4. out = att @ Wproj + b     (2048 x 1280, K=1280)
    gemm_bias_kernel<<<dim3(HID / 64, T / 64), 256>>>(p_att, projW, projB, out, T, HID, HID);
}

// round 4
// speedup vs baseline: 1.4898x; 1.4898x over previous
#include <cuda_runtime.h>
#include <cuda_bf16.h>
#include <cstdint>
#include <math.h>

#define T 2048
#define HID 1280
#define NH 16
#define HD 80
#define THID (3*HID)

// ---------------- scratch (static device allocations only) ----------------
__device__ float g_qkv[T*THID];
__device__ float g_q[NH*T*HD];
__device__ float g_k[NH*T*HD];
__device__ float g_v[NH*T*HD];
__device__ float g_att[T*HID];

__device__ __nv_bfloat16 g_xh[T*HID],    g_xl[T*HID];        // x hi/lo
__device__ __nv_bfloat16 g_wqh[THID*HID], g_wql[THID*HID];   // Wqkv^T [3840][1280]
__device__ __nv_bfloat16 g_wph[HID*HID],  g_wpl[HID*HID];    // Wproj^T [1280][1280]
__device__ __nv_bfloat16 g_ah[T*HID],    g_al[T*HID];        // att hi/lo

// ---------------- helpers (arch-neutral: mma.sync / ldmatrix / cp.async) ---
__device__ __forceinline__ uint32_t smem_to_u32(const void* p) {
    uint32_t a;
    asm("{ .reg .u64 tmp; cvta.to.shared.u64 tmp, %1; cvt.u32.u64 %0, tmp; }"
        : "=r"(a) : "l"(p));
    return a;
}
__device__ __forceinline__ void mma_bf16(float* c, const uint32_t* a, const uint32_t* b) {
    asm volatile("mma.sync.aligned.m16n8k16.row.col.f32.bf16.bf16.f32 "
        "{%0,%1,%2,%3}, {%4,%5,%6,%7}, {%8,%9}, {%0,%1,%2,%3};"
        : "+f"(c[0]), "+f"(c[1]), "+f"(c[2]), "+f"(c[3])
        : "r"(a[0]), "r"(a[1]), "r"(a[2]), "r"(a[3]), "r"(b[0]), "r"(b[1]));
}
__device__ __forceinline__ void ldsm_x4(uint32_t* r, uint32_t addr) {
    asm volatile("ldmatrix.sync.aligned.m8n8.x4.shared.b16 {%0,%1,%2,%3}, [%4];"
        : "=r"(r[0]), "=r"(r[1]), "=r"(r[2]), "=r"(r[3]) : "r"(addr));
}
__device__ __forceinline__ void cp_async16(uint32_t dst, const void* src) {
    asm volatile("cp.async.cg.shared.global [%0], [%1], 16;" :: "r"(dst), "l"(src));
}
#define CP_COMMIT() asm volatile("cp.async.commit_group;" ::: "memory")
#define CP_WAIT1()  asm volatile("cp.async.wait_group 1;" ::: "memory")

// ---------------------------------------------------------------------------
// fp32 -> bf16 hi + bf16 lo split
// ---------------------------------------------------------------------------
__global__ void convert_split_kernel(const float* __restrict__ src,
                                     __nv_bfloat16* __restrict__ h,
                                     __nv_bfloat16* __restrict__ l, int n)
{
    int i = blockIdx.x * blockDim.x + threadIdx.x;
    if (i >= n) return;
    float v = src[i];
    __nv_bfloat16 hh = __float2bfloat16_rn(v);
    h[i] = hh;
    l[i] = __float2bfloat16_rn(v - __bfloat162float(hh));
}

// Transpose [K][N] -> [N][K] and split into hi/lo bf16.
__global__ void convert_splitT_kernel(const float* __restrict__ src,
                                      __nv_bfloat16* __restrict__ h,
                                      __nv_bfloat16* __restrict__ l,
                                      int K, int N)
{
    __shared__ float t[32][33];
    int nb = blockIdx.x * 32, kb = blockIdx.y * 32;
    int tx = threadIdx.x, ty = threadIdx.y;   // block (32,8)
    #pragma unroll
    for (int j = 0; j < 4; j++)
        t[ty + j * 8][tx] = src[(size_t)(kb + ty + j * 8) * N + nb + tx];
    __syncthreads();
    #pragma unroll
    for (int j = 0; j < 4; j++) {
        float v = t[tx][ty + j * 8];
        __nv_bfloat16 hh = __float2bfloat16_rn(v);
        size_t o = (size_t)(nb + ty + j * 8) * K + kb + tx;
        h[o] = hh;
        l[o] = __float2bfloat16_rn(v - __bfloat162float(hh));
    }
}

// ---------------------------------------------------------------------------
// Split-bf16 tensor-core GEMM via mma.sync:
//   C[M,N] = (Ah+Al)[M,K] @ (Bh+Bl)[N,K]^T + bias
// 128x128 block tile, BK=32, 2-stage cp.async pipeline, 8 warps (32x64 each).
// ---------------------------------------------------------------------------
#define BM 128
#define BN 128
#define BK 32
#define ASTRIDE 40                     // bf16 elems per smem row (80B, pad)
#define TILE_B (128*ASTRIDE*2)         // 10240 B per tile
#define STAGE_B (4*TILE_B)             // Ah, Al, Bh, Bl
#define GEMM_SMEM (2*STAGE_B)          // 81920 B

__global__ __launch_bounds__(256, 2)
void gemm_bf16split_kernel(const __nv_bfloat16* __restrict__ Ah,
                           const __nv_bfloat16* __restrict__ Al,
                           const __nv_bfloat16* __restrict__ Bh,
                           const __nv_bfloat16* __restrict__ Bl,
                           const float* __restrict__ bias,
                           float* __restrict__ C,
                           int M, int N, int K)
{
    extern __shared__ char sm[];
    const uint32_t sbase = smem_to_u32(sm);

    const int tid  = threadIdx.x;
    const int wid  = tid >> 5;
    const int lane = tid & 31;
    const int m0 = blockIdx.y * BM, n0 = blockIdx.x * BN;
    const int wm = (wid >> 1) * 32;       // warp row offset in tile
    const int wn = (wid & 1) * 64;        // warp col offset in tile

    float acc[2][8][4];
    #pragma unroll
    for (int a = 0; a < 2; a++)
        #pragma unroll
        for (int b = 0; b < 8; b++)
            #pragma unroll
            for (int c = 0; c < 4; c++) acc[a][b][c] = 0.f;

    // cp.async mapping: thread handles rows r and r+64, one 16B chunk each
    const int c_row = tid >> 2;            // 0..63
    const int c_col = (tid & 3) * 8;       // bf16 col: 0,8,16,24
    const uint32_t s_off  = (uint32_t)(c_row * ASTRIDE + c_col) * 2;
    const uint32_t s_off2 = s_off + 64 * ASTRIDE * 2;

    const __nv_bfloat16* gAh = Ah + (size_t)(m0 + c_row) * K + c_col;
    const __nv_bfloat16* gAl = Al + (size_t)(m0 + c_row) * K + c_col;
    const __nv_bfloat16* gBh = Bh + (size_t)(n0 + c_row) * K + c_col;
    const __nv_bfloat16* gBl = Bl + (size_t)(n0 + c_row) * K + c_col;
    const size_t g2 = (size_t)64 * K;

    const int niter = K / BK;

    // prologue: stage 0
    {
        uint32_t sb = sbase;
        cp_async16(sb + s_off,                       gAh);
        cp_async16(sb + s_off2,                      gAh + g2);
        cp_async16(sb + TILE_B + s_off,              gAl);
        cp_async16(sb + TILE_B + s_off2,             gAl + g2);
        cp_async16(sb + 2*TILE_B + s_off,            gBh);
        cp_async16(sb + 2*TILE_B + s_off2,           gBh + g2);
        cp_async16(sb + 3*TILE_B + s_off,            gBl);
        cp_async16(sb + 3*TILE_B + s_off2,           gBl + g2);
    }
    CP_COMMIT();

    // ldmatrix address components (byte offsets within a tile)
    const int a_row = (lane & 15);
    const int a_colb = ((lane >> 4) << 3) * 2;         // +8 bf16 for lanes>=16
    const int b_row = (lane & 7) + ((lane >> 4) << 3);
    const int b_colb = (((lane >> 3) & 1) << 3) * 2;

    for (int it = 0; it < niter; it++) {
        int nk = it + 1;
        if (nk < niter) {
            uint32_t sb = sbase + (nk & 1) * STAGE_B;
            int k0 = nk * BK;
            cp_async16(sb + s_off,             gAh + k0);
            cp_async16(sb + s_off2,            gAh + g2 + k0);
            cp_async16(sb + TILE_B + s_off,    gAl + k0);
            cp_async16(sb + TILE_B + s_off2,   gAl + g2 + k0);
            cp_async16(sb + 2*TILE_B + s_off,  gBh + k0);
            cp_async16(sb + 2*TILE_B + s_off2, gBh + g2 + k0);
            cp_async16(sb + 3*TILE_B + s_off,  gBl + k0);
            cp_async16(sb + 3*TILE_B + s_off2, gBl + g2 + k0);
        }
        CP_COMMIT();
        CP_WAIT1();
        __syncthreads();

        const uint32_t sb = sbase + (it & 1) * STAGE_B;
        const uint32_t sAh = sb;
        const uint32_t sAl = sb + TILE_B;
        const uint32_t sBh = sb + 2*TILE_B;
        const uint32_t sBl = sb + 3*TILE_B;

        #pragma unroll
        for (int k16 = 0; k16 < 2; k16++) {
            const int kcb = k16 * 32;   // 16 bf16 = 32 bytes
            uint32_t ah[2][4], al[2][4];
            #pragma unroll
            for (int mi = 0; mi < 2; mi++) {
                uint32_t ro = (uint32_t)(wm + mi*16 + a_row) * (ASTRIDE*2) + kcb + a_colb;
                ldsm_x4(ah[mi], sAh + ro);
                ldsm_x4(al[mi], sAl + ro);
            }
            #pragma unroll
            for (int g = 0; g < 4; g++) {
                uint32_t ro = (uint32_t)(wn + g*16 + b_row) * (ASTRIDE*2) + kcb + b_colb;
                uint32_t bh[4], bl[4];
                ldsm_x4(bh, sBh + ro);
                ldsm_x4(bl, sBl + ro);
                #pragma unroll
                for (int mi = 0; mi < 2; mi++) {
                    mma_bf16(acc[mi][g*2+0], ah[mi], bh + 0);
                    mma_bf16(acc[mi][g*2+0], ah[mi], bl + 0);
                    mma_bf16(acc[mi][g*2+0], al[mi], bh + 0);
                    mma_bf16(acc[mi][g*2+1], ah[mi], bh + 2);
                    mma_bf16(acc[mi][g*2+1], ah[mi], bl + 2);
                    mma_bf16(acc[mi][g*2+1], al[mi], bh + 2);
                }
            }
        }
        __syncthreads();
    }

    // Epilogue: bias add + store (c0,c1 -> row, c2,c3 -> row+8)
    #pragma unroll
    for (int mi = 0; mi < 2; mi++) {
        int r0 = m0 + wm + mi*16 + (lane >> 2);
        #pragma unroll
        for (int t = 0; t < 8; t++) {
            int col = n0 + wn + t*8 + (lane & 3)*2;
            float b0 = bias[col], b1 = bias[col + 1];
            float2 v0 = { acc[mi][t][0] + b0, acc[mi][t][1] + b1 };
            float2 v1 = { acc[mi][t][2] + b0, acc[mi][t][3] + b1 };
            *(float2*)(C + (size_t)r0 * N + col)       = v0;
            *(float2*)(C + (size_t)(r0 + 8) * N + col) = v1;
        }
    }
}

// ---------------------------------------------------------------------------
// RoPE + split qkv into per-head [head][T][80] buffers.
// ---------------------------------------------------------------------------
__global__ void rope_split_kernel(const float* __restrict__ rope)
{
    int idx = blockIdx.x * blockDim.x + threadIdx.x;
    if (idx >= T * NH * HD) return;
    int d = idx % HD;
    int n = (idx / HD) % NH;
    int t = idx / (HD * NH);

    int dr = (d < 40) ? d : d - 40;
    float ang = rope[t * 40 + dr];
    float c = cosf(ang), s = sinf(ang);

    const float* qrow = g_qkv + (size_t)t * THID + n * HD;
    float qv, kv;
    if (d < 40) {
        qv = qrow[d] * c        - qrow[d + 40] * s;
        kv = qrow[HID + d] * c  - qrow[HID + d + 40] * s;
    } else {
        qv = qrow[d - 40] * s       + qrow[d] * c;
        kv = qrow[HID + d - 40] * s + qrow[HID + d] * c;
    }
    int o = (n * T + t) * HD + d;
    g_q[o] = qv;
    g_k[o] = kv;
    g_v[o] = qrow[2 * HID + d];
}

// ---------------------------------------------------------------------------
// Flash attention with block-diagonal masking (unchanged; correct at 1e-6).
// ---------------------------------------------------------------------------
__global__ void attn_kernel(const int* __restrict__ seg)
{
    const int n = blockIdx.y;
    const int q0 = blockIdx.x * 64;
    const int tid = threadIdx.x;
    const int row = tid >> 2;
    const int sub = tid & 3;

    __shared__ float Qs[64 * HD];
    __shared__ float Ks[32 * HD];
    __shared__ float Vs[32 * HD];
    __shared__ int   segk[32];

    const float* qbase = g_q + (size_t)(n * T + q0) * HD;
    for (int i = tid; i < 64 * HD; i += 256) Qs[i] = qbase[i];

    const int myseg  = seg[q0 + row];
    const int seg_lo = seg[q0];
    const int seg_hi = seg[q0 + 63];

    int lo = 0, hi = T;
    while (lo < hi) { int mid = (lo + hi) >> 1; if (seg[mid] < seg_lo) lo = mid + 1; else hi = mid; }
    const int kstart = lo;
    hi = T;
    while (lo < hi) { int mid = (lo + hi) >> 1; if (seg[mid] <= seg_hi) lo = mid + 1; else hi = mid; }
    const int kend = lo;

    float m = -1e30f, l = 0.f;
    float accv[20];
    #pragma unroll
    for (int i = 0; i < 20; i++) accv[i] = 0.f;
    const float scale = 0.11180339887498949f;

    for (int kb = kstart & ~31; kb < kend; kb += 32) {
        __syncthreads();
        for (int i = tid; i < 32 * HD; i += 256) {
            int kk = i / HD, d = i % HD;
            int kg = kb + kk;
            float kvv = 0.f, vvv = 0.f;
            if (kg < kend) {
                kvv = g_k[(size_t)(n * T + kg) * HD + d];
                vvv = g_v[(size_t)(n * T + kg) * HD + d];
            }
            Ks[i] = kvv; Vs[i] = vvv;
        }
        if (tid < 32) segk[tid] = (kb + tid < T) ? seg[kb + tid] : -1;
        __syncthreads();

        float sc[8];
        unsigned vb = 0;
        #pragma unroll
        for (int jj = 0; jj < 8; jj++) {
            int kk = jj * 4 + sub;
            int kg = kb + kk;
            const float4* qr = (const float4*)(Qs + row * HD);
            const float4* kr = (const float4*)(Ks + kk * HD);
            float s = 0.f;
            #pragma unroll
            for (int d4 = 0; d4 < 20; d4++) {
                float4 a = qr[d4], b = kr[d4];
                s += a.x * b.x + a.y * b.y + a.z * b.z + a.w * b.w;
            }
            sc[jj] = s * scale;
            if (kg >= kstart && kg < kend && segk[kk] == myseg) vb |= (1u << jj);
        }

        float cm = -1e30f;
        #pragma unroll
        for (int jj = 0; jj < 8; jj++) if (vb & (1u << jj)) cm = fmaxf(cm, sc[jj]);
        cm = fmaxf(cm, __shfl_xor_sync(0xffffffffu, cm, 1));
        cm = fmaxf(cm, __shfl_xor_sync(0xffffffffu, cm, 2));
        float mnew = fmaxf(m, cm);
        float factor = __expf(m - mnew);
        m = mnew;
        l *= factor;
        #pragma unroll
        for (int i = 0; i < 20; i++) accv[i] *= factor;

        float p[8];
        #pragma unroll
        for (int jj = 0; jj < 8; jj++) {
            p[jj] = (vb & (1u << jj)) ? __expf(sc[jj] - m) : 0.f;
            l += p[jj];
        }

        #pragma unroll
        for (int jj = 0; jj < 8; jj++) {
            #pragma unroll
            for (int src = 0; src < 4; src++) {
                float pj = __shfl_sync(0xffffffffu, p[jj], src, 4);
                int kk = jj * 4 + src;
                const float* vr = Vs + kk * HD + sub * 20;
                #pragma unroll
                for (int i = 0; i < 20; i++) accv[i] += pj * vr[i];
            }
        }
    }

    l += __shfl_xor_sync(0xffffffffu, l, 1);
    l += __shfl_xor_sync(0xffffffffu, l, 2);
    float inv = 1.f / l;

    float* o = g_att + (size_t)(q0 + row) * HID + n * HD + sub * 20;
    #pragma unroll
    for (int i = 0; i < 20; i++) o[i] = accv[i] * inv;
}

// ---------------------------------------------------------------------------
extern "C" void kernel_launch(void* const* d_in, const int* in_sizes, int n_in,
                              void* d_out, int out_size)
{
    const float* x     = (const float*)d_in[0];
    const float* rope  = (const float*)d_in[1];
    const int*   seg   = (const int*)  d_in[2];
    const float* qkvW  = (const float*)d_in[3];
    const float* qkvB  = (const float*)d_in[4];
    const float* projW = (const float*)d_in[5];
    const float* projB = (const float*)d_in[6];
    float* out = (float*)d_out;

    float *p_qkv, *p_att;
    cudaGetSymbolAddress((void**)&p_qkv, g_qkv);
    cudaGetSymbolAddress((void**)&p_att, g_att);
    __nv_bfloat16 *p_xh, *p_xl, *p_wqh, *p_wql, *p_wph, *p_wpl, *p_ah, *p_al;
    cudaGetSymbolAddress((void**)&p_xh, g_xh);   cudaGetSymbolAddress((void**)&p_xl, g_xl);
    cudaGetSymbolAddress((void**)&p_wqh, g_wqh); cudaGetSymbolAddress((void**)&p_wql, g_wql);
    cudaGetSymbolAddress((void**)&p_wph, g_wph); cudaGetSymbolAddress((void**)&p_wpl, g_wpl);
    cudaGetSymbolAddress((void**)&p_ah, g_ah);   cudaGetSymbolAddress((void**)&p_al, g_al);

    cudaFuncSetAttribute(gemm_bf16split_kernel,
                         cudaFuncAttributeMaxDynamicSharedMemorySize, GEMM_SMEM);

    // 0. convert inputs to split-bf16 (weights transposed to [N][K])
    convert_split_kernel<<<(T*HID + 255)/256, 256>>>(x, p_xh, p_xl, T*HID);
    convert_splitT_kernel<<<dim3(THID/32, HID/32), dim3(32, 8)>>>(qkvW, p_wqh, p_wql, HID, THID);
    convert_splitT_kernel<<<dim3(HID/32, HID/32), dim3(32, 8)>>>(projW, p_wph, p_wpl, HID, HID);

    // 1. qkv = x @ Wqkv + b   (mma.sync split-bf16)
    gemm_bf16split_kernel<<<dim3(THID/BN, T/BM), 256, GEMM_SMEM>>>(
        p_xh, p_xl, p_wqh, p_wql, qkvB, p_qkv, T, THID, HID);

    // 2. RoPE + split into per-head Q,K,V
    rope_split_kernel<<<(T*NH*HD + 255)/256, 256>>>(rope);

    // 3. Block-diagonal flash attention (fp32)
    attn_kernel<<<dim3(T/64, NH), 256>>>(seg);

    // 4. convert attention output, then out = att @ Wproj + b
    convert_split_kernel<<<(T*HID + 255)/256, 256>>>(p_att, p_ah, p_al, T*HID);
    gemm_bf16split_kernel<<<dim3(HID/BN, T/BM), 256, GEMM_SMEM>>>(
        p_ah, p_al, p_wph, p_wpl, projB, out, T, HID, HID);
}

// round 5
// speedup vs baseline: 1.9162x; 1.2862x over previous
#include <cuda_runtime.h>
#include <cuda_bf16.h>
#include <cstdint>
#include <math.h>

#define T 2048
#define HID 1280
#define NH 16
#define HD 80
#define THID (3*HID)

// ---------------- scratch (static device allocations only) ----------------
__device__ float g_qkv[T*THID];
__device__ float g_q[NH*T*HD];
__device__ float g_k[NH*T*HD];
__device__ float g_v[NH*T*HD];
__device__ float g_att[T*HID];

__device__ __nv_bfloat16 g_xh[T*HID],    g_xl[T*HID];        // x hi/lo
__device__ __nv_bfloat16 g_wqh[THID*HID], g_wql[THID*HID];   // Wqkv^T [3840][1280]
__device__ __nv_bfloat16 g_wph[HID*HID],  g_wpl[HID*HID];    // Wproj^T [1280][1280]
__device__ __nv_bfloat16 g_ah[T*HID],    g_al[T*HID];        // att hi/lo

// ---------------- helpers (arch-neutral: mma.sync / ldmatrix / cp.async) ---
__device__ __forceinline__ uint32_t smem_to_u32(const void* p) {
    uint32_t a;
    asm("{ .reg .u64 tmp; cvta.to.shared.u64 tmp, %1; cvt.u32.u64 %0, tmp; }"
        : "=r"(a) : "l"(p));
    return a;
}
__device__ __forceinline__ void mma_bf16(float* c, const uint32_t* a, const uint32_t* b) {
    asm volatile("mma.sync.aligned.m16n8k16.row.col.f32.bf16.bf16.f32 "
        "{%0,%1,%2,%3}, {%4,%5,%6,%7}, {%8,%9}, {%0,%1,%2,%3};"
        : "+f"(c[0]), "+f"(c[1]), "+f"(c[2]), "+f"(c[3])
        : "r"(a[0]), "r"(a[1]), "r"(a[2]), "r"(a[3]), "r"(b[0]), "r"(b[1]));
}
__device__ __forceinline__ void ldsm_x4(uint32_t* r, uint32_t addr) {
    asm volatile("ldmatrix.sync.aligned.m8n8.x4.shared.b16 {%0,%1,%2,%3}, [%4];"
        : "=r"(r[0]), "=r"(r[1]), "=r"(r[2]), "=r"(r[3]) : "r"(addr));
}
__device__ __forceinline__ void cp_async16(uint32_t dst, const void* src) {
    asm volatile("cp.async.cg.shared.global [%0], [%1], 16;" :: "r"(dst), "l"(src));
}
#define CP_COMMIT() asm volatile("cp.async.commit_group;" ::: "memory")
#define CP_WAIT1()  asm volatile("cp.async.wait_group 1;" ::: "memory")

// ---------------------------------------------------------------------------
// fp32 -> bf16 hi + bf16 lo split
// ---------------------------------------------------------------------------
__global__ void convert_split_kernel(const float* __restrict__ src,
                                     __nv_bfloat16* __restrict__ h,
                                     __nv_bfloat16* __restrict__ l, int n)
{
    int i = blockIdx.x * blockDim.x + threadIdx.x;
    if (i >= n) return;
    float v = src[i];
    __nv_bfloat16 hh = __float2bfloat16_rn(v);
    h[i] = hh;
    l[i] = __float2bfloat16_rn(v - __bfloat162float(hh));
}

// Transpose [K][N] -> [N][K] and split into hi/lo bf16.
__global__ void convert_splitT_kernel(const float* __restrict__ src,
                                      __nv_bfloat16* __restrict__ h,
                                      __nv_bfloat16* __restrict__ l,
                                      int K, int N)
{
    __shared__ float t[32][33];
    int nb = blockIdx.x * 32, kb = blockIdx.y * 32;
    int tx = threadIdx.x, ty = threadIdx.y;   // block (32,8)
    #pragma unroll
    for (int j = 0; j < 4; j++)
        t[ty + j * 8][tx] = src[(size_t)(kb + ty + j * 8) * N + nb + tx];
    __syncthreads();
    #pragma unroll
    for (int j = 0; j < 4; j++) {
        float v = t[tx][ty + j * 8];
        __nv_bfloat16 hh = __float2bfloat16_rn(v);
        size_t o = (size_t)(nb + ty + j * 8) * K + kb + tx;
        h[o] = hh;
        l[o] = __float2bfloat16_rn(v - __bfloat162float(hh));
    }
}

// ---------------------------------------------------------------------------
// Split-bf16 tensor-core GEMM via mma.sync (unchanged from round 4).
// ---------------------------------------------------------------------------
#define BM 128
#define BN 128
#define BK 32
#define ASTRIDE 40
#define TILE_B (128*ASTRIDE*2)
#define STAGE_B (4*TILE_B)
#define GEMM_SMEM (2*STAGE_B)

__global__ __launch_bounds__(256, 2)
void gemm_bf16split_kernel(const __nv_bfloat16* __restrict__ Ah,
                           const __nv_bfloat16* __restrict__ Al,
                           const __nv_bfloat16* __restrict__ Bh,
                           const __nv_bfloat16* __restrict__ Bl,
                           const float* __restrict__ bias,
                           float* __restrict__ C,
                           int M, int N, int K)
{
    extern __shared__ char sm[];
    const uint32_t sbase = smem_to_u32(sm);

    const int tid  = threadIdx.x;
    const int wid  = tid >> 5;
    const int lane = tid & 31;
    const int m0 = blockIdx.y * BM, n0 = blockIdx.x * BN;
    const int wm = (wid >> 1) * 32;
    const int wn = (wid & 1) * 64;

    float acc[2][8][4];
    #pragma unroll
    for (int a = 0; a < 2; a++)
        #pragma unroll
        for (int b = 0; b < 8; b++)
            #pragma unroll
            for (int c = 0; c < 4; c++) acc[a][b][c] = 0.f;

    const int c_row = tid >> 2;
    const int c_col = (tid & 3) * 8;
    const uint32_t s_off  = (uint32_t)(c_row * ASTRIDE + c_col) * 2;
    const uint32_t s_off2 = s_off + 64 * ASTRIDE * 2;

    const __nv_bfloat16* gAh = Ah + (size_t)(m0 + c_row) * K + c_col;
    const __nv_bfloat16* gAl = Al + (size_t)(m0 + c_row) * K + c_col;
    const __nv_bfloat16* gBh = Bh + (size_t)(n0 + c_row) * K + c_col;
    const __nv_bfloat16* gBl = Bl + (size_t)(n0 + c_row) * K + c_col;
    const size_t g2 = (size_t)64 * K;

    const int niter = K / BK;

    {
        uint32_t sb = sbase;
        cp_async16(sb + s_off,             gAh);
        cp_async16(sb + s_off2,            gAh + g2);
        cp_async16(sb + TILE_B + s_off,    gAl);
        cp_async16(sb + TILE_B + s_off2,   gAl + g2);
        cp_async16(sb + 2*TILE_B + s_off,  gBh);
        cp_async16(sb + 2*TILE_B + s_off2, gBh + g2);
        cp_async16(sb + 3*TILE_B + s_off,  gBl);
        cp_async16(sb + 3*TILE_B + s_off2, gBl + g2);
    }
    CP_COMMIT();

    const int a_row = (lane & 15);
    const int a_colb = ((lane >> 4) << 3) * 2;
    const int b_row = (lane & 7) + ((lane >> 4) << 3);
    const int b_colb = (((lane >> 3) & 1) << 3) * 2;

    for (int it = 0; it < niter; it++) {
        int nk = it + 1;
        if (nk < niter) {
            uint32_t sb = sbase + (nk & 1) * STAGE_B;
            int k0 = nk * BK;
            cp_async16(sb + s_off,             gAh + k0);
            cp_async16(sb + s_off2,            gAh + g2 + k0);
            cp_async16(sb + TILE_B + s_off,    gAl + k0);
            cp_async16(sb + TILE_B + s_off2,   gAl + g2 + k0);
            cp_async16(sb + 2*TILE_B + s_off,  gBh + k0);
            cp_async16(sb + 2*TILE_B + s_off2, gBh + g2 + k0);
            cp_async16(sb + 3*TILE_B + s_off,  gBl + k0);
            cp_async16(sb + 3*TILE_B + s_off2, gBl + g2 + k0);
        }
        CP_COMMIT();
        CP_WAIT1();
        __syncthreads();

        const uint32_t sb = sbase + (it & 1) * STAGE_B;
        const uint32_t sAh = sb;
        const uint32_t sAl = sb + TILE_B;
        const uint32_t sBh = sb + 2*TILE_B;
        const uint32_t sBl = sb + 3*TILE_B;

        #pragma unroll
        for (int k16 = 0; k16 < 2; k16++) {
            const int kcb = k16 * 32;
            uint32_t ah[2][4], al[2][4];
            #pragma unroll
            for (int mi = 0; mi < 2; mi++) {
                uint32_t ro = (uint32_t)(wm + mi*16 + a_row) * (ASTRIDE*2) + kcb + a_colb;
                ldsm_x4(ah[mi], sAh + ro);
                ldsm_x4(al[mi], sAl + ro);
            }
            #pragma unroll
            for (int g = 0; g < 4; g++) {
                uint32_t ro = (uint32_t)(wn + g*16 + b_row) * (ASTRIDE*2) + kcb + b_colb;
                uint32_t bh[4], bl[4];
                ldsm_x4(bh, sBh + ro);
                ldsm_x4(bl, sBl + ro);
                #pragma unroll
                for (int mi = 0; mi < 2; mi++) {
                    mma_bf16(acc[mi][g*2+0], ah[mi], bh + 0);
                    mma_bf16(acc[mi][g*2+0], ah[mi], bl + 0);
                    mma_bf16(acc[mi][g*2+0], al[mi], bh + 0);
                    mma_bf16(acc[mi][g*2+1], ah[mi], bh + 2);
                    mma_bf16(acc[mi][g*2+1], ah[mi], bl + 2);
                    mma_bf16(acc[mi][g*2+1], al[mi], bh + 2);
                }
            }
        }
        __syncthreads();
    }

    #pragma unroll
    for (int mi = 0; mi < 2; mi++) {
        int r0 = m0 + wm + mi*16 + (lane >> 2);
        #pragma unroll
        for (int t = 0; t < 8; t++) {
            int col = n0 + wn + t*8 + (lane & 3)*2;
            float b0 = bias[col], b1 = bias[col + 1];
            float2 v0 = { acc[mi][t][0] + b0, acc[mi][t][1] + b1 };
            float2 v1 = { acc[mi][t][2] + b0, acc[mi][t][3] + b1 };
            *(float2*)(C + (size_t)r0 * N + col)       = v0;
            *(float2*)(C + (size_t)(r0 + 8) * N + col) = v1;
        }
    }
}

// ---------------------------------------------------------------------------
// RoPE + split qkv into per-head [head][T][80] buffers.
// ---------------------------------------------------------------------------
__global__ void rope_split_kernel(const float* __restrict__ rope)
{
    int idx = blockIdx.x * blockDim.x + threadIdx.x;
    if (idx >= T * NH * HD) return;
    int d = idx % HD;
    int n = (idx / HD) % NH;
    int t = idx / (HD * NH);

    int dr = (d < 40) ? d : d - 40;
    float ang = rope[t * 40 + dr];
    float c = cosf(ang), s = sinf(ang);

    const float* qrow = g_qkv + (size_t)t * THID + n * HD;
    float qv, kv;
    if (d < 40) {
        qv = qrow[d] * c        - qrow[d + 40] * s;
        kv = qrow[HID + d] * c  - qrow[HID + d + 40] * s;
    } else {
        qv = qrow[d - 40] * s       + qrow[d] * c;
        kv = qrow[HID + d - 40] * s + qrow[HID + d] * c;
    }
    int o = (n * T + t) * HD + d;
    g_q[o] = qv;
    g_k[o] = kv;
    g_v[o] = qrow[2 * HID + d];
}

// ---------------------------------------------------------------------------
// Flash attention, block-diagonal masking.
// CHANGES vs round 4:
//  - smem row stride padded 80 -> 84 floats: per-warp Q-row accesses now hit
//    8 disjoint 4-bank groups (r*84 mod 32 = 0,20,8,28,16,4,24,12) instead of
//    4-way conflicting; K/V accesses likewise conflict-free.
//  - K/V tiles double-buffered: one __syncthreads per tile, prefetch overlaps
//    global loads with compute.
// ---------------------------------------------------------------------------
#define AST 84
#define ATT_SMEM ((64*AST + 4*32*AST) * 4 + 2*32*4)

__global__ __launch_bounds__(256)
void attn_kernel(const int* __restrict__ seg)
{
    extern __shared__ char asm_raw[];
    float* Qs = (float*)asm_raw;                      // 64*AST
    float* Ks = Qs + 64*AST;                          // 2 * 32*AST
    float* Vs = Ks + 2*32*AST;                        // 2 * 32*AST
    int*   segk = (int*)(Vs + 2*32*AST);              // 2 * 32

    const int n = blockIdx.y;
    const int q0 = blockIdx.x * 64;
    const int tid = threadIdx.x;
    const int row = tid >> 2;
    const int sub = tid & 3;

    // Load Q tile (padded stride)
    const float* qbase = g_q + (size_t)(n * T + q0) * HD;
    for (int i = tid; i < 64 * HD; i += 256) {
        int r = i / HD, d = i % HD;
        Qs[r * AST + d] = qbase[i];
    }

    const int myseg  = seg[q0 + row];
    const int seg_lo = seg[q0];
    const int seg_hi = seg[q0 + 63];

    int lo = 0, hi = T;
    while (lo < hi) { int mid = (lo + hi) >> 1; if (seg[mid] < seg_lo) lo = mid + 1; else hi = mid; }
    const int kstart = lo;
    hi = T;
    while (lo < hi) { int mid = (lo + hi) >> 1; if (seg[mid] <= seg_hi) lo = mid + 1; else hi = mid; }
    const int kend = lo;

    const int kb0 = kstart & ~31;
    const int n_tiles = (kend - kb0 + 31) >> 5;

    // prefetch tile 0 into buffer 0
    {
        const int kb = kb0;
        float* Kd = Ks; float* Vd = Vs;
        for (int i = tid; i < 32 * HD; i += 256) {
            int kk = i / HD, d = i % HD;
            int kg = kb + kk;
            float kvv = 0.f, vvv = 0.f;
            if (kg < kend) {
                kvv = g_k[(size_t)(n * T + kg) * HD + d];
                vvv = g_v[(size_t)(n * T + kg) * HD + d];
            }
            Kd[kk * AST + d] = kvv; Vd[kk * AST + d] = vvv;
        }
        if (tid < 32) segk[tid] = (kb + tid < T) ? seg[kb + tid] : -1;
    }
    __syncthreads();

    float m = -1e30f, l = 0.f;
    float accv[20];
    #pragma unroll
    for (int i = 0; i < 20; i++) accv[i] = 0.f;
    const float scale = 0.11180339887498949f;

    for (int t = 0; t < n_tiles; t++) {
        const int buf = t & 1;
        const int kb = kb0 + t * 32;

        // prefetch next tile into the other buffer (no hazard: its previous
        // readers were protected by the sync at the end of iteration t-1)
        if (t + 1 < n_tiles) {
            const int kb2 = kb + 32;
            float* Kd = Ks + ((t + 1) & 1) * 32 * AST;
            float* Vd = Vs + ((t + 1) & 1) * 32 * AST;
            for (int i = tid; i < 32 * HD; i += 256) {
                int kk = i / HD, d = i % HD;
                int kg = kb2 + kk;
                float kvv = 0.f, vvv = 0.f;
                if (kg < kend) {
                    kvv = g_k[(size_t)(n * T + kg) * HD + d];
                    vvv = g_v[(size_t)(n * T + kg) * HD + d];
                }
                Kd[kk * AST + d] = kvv; Vd[kk * AST + d] = vvv;
            }
            if (tid < 32) segk[((t + 1) & 1) * 32 + tid] = (kb2 + tid < T) ? seg[kb2 + tid] : -1;
        }

        const float* Kb = Ks + buf * 32 * AST;
        const float* Vb = Vs + buf * 32 * AST;
        const int*   sg = segk + buf * 32;

        float sc[8];
        unsigned vb = 0;
        #pragma unroll
        for (int jj = 0; jj < 8; jj++) {
            int kk = jj * 4 + sub;
            int kg = kb + kk;
            const float4* qr = (const float4*)(Qs + row * AST);
            const float4* kr = (const float4*)(Kb + kk * AST);
            float s = 0.f;
            #pragma unroll
            for (int d4 = 0; d4 < 20; d4++) {
                float4 a = qr[d4], b = kr[d4];
                s += a.x * b.x + a.y * b.y + a.z * b.z + a.w * b.w;
            }
            sc[jj] = s * scale;
            if (kg >= kstart && kg < kend && sg[kk] == myseg) vb |= (1u << jj);
        }

        float cm = -1e30f;
        #pragma unroll
        for (int jj = 0; jj < 8; jj++) if (vb & (1u << jj)) cm = fmaxf(cm, sc[jj]);
        cm = fmaxf(cm, __shfl_xor_sync(0xffffffffu, cm, 1));
        cm = fmaxf(cm, __shfl_xor_sync(0xffffffffu, cm, 2));
        float mnew = fmaxf(m, cm);
        float factor = __expf(m - mnew);
        m = mnew;
        l *= factor;
        #pragma unroll
        for (int i = 0; i < 20; i++) accv[i] *= factor;

        float p[8];
        #pragma unroll
        for (int jj = 0; jj < 8; jj++) {
            p[jj] = (vb & (1u << jj)) ? __expf(sc[jj] - m) : 0.f;
            l += p[jj];
        }

        #pragma unroll
        for (int jj = 0; jj < 8; jj++) {
            #pragma unroll
            for (int src = 0; src < 4; src++) {
                float pj = __shfl_sync(0xffffffffu, p[jj], src, 4);
                int kk = jj * 4 + src;
                const float* vr = Vb + kk * AST + sub * 20;
                #pragma unroll
                for (int i = 0; i < 20; i++) accv[i] += pj * vr[i];
            }
        }
        __syncthreads();
    }

    l += __shfl_xor_sync(0xffffffffu, l, 1);
    l += __shfl_xor_sync(0xffffffffu, l, 2);
    float inv = 1.f / l;

    float* o = g_att + (size_t)(q0 + row) * HID + n * HD + sub * 20;
    #pragma unroll
    for (int i = 0; i < 20; i++) o[i] = accv[i] * inv;
}

// ---------------------------------------------------------------------------
extern "C" void kernel_launch(void* const* d_in, const int* in_sizes, int n_in,
                              void* d_out, int out_size)
{
    const float* x     = (const float*)d_in[0];
    const float* rope  = (const float*)d_in[1];
    const int*   seg   = (const int*)  d_in[2];
    const float* qkvW  = (const float*)d_in[3];
    const float* qkvB  = (const float*)d_in[4];
    const float* projW = (const float*)d_in[5];
    const float* projB = (const float*)d_in[6];
    float* out = (float*)d_out;

    float *p_qkv, *p_att;
    cudaGetSymbolAddress((void**)&p_qkv, g_qkv);
    cudaGetSymbolAddress((void**)&p_att, g_att);
    __nv_bfloat16 *p_xh, *p_xl, *p_wqh, *p_wql, *p_wph, *p_wpl, *p_ah, *p_al;
    cudaGetSymbolAddress((void**)&p_xh, g_xh);   cudaGetSymbolAddress((void**)&p_xl, g_xl);
    cudaGetSymbolAddress((void**)&p_wqh, g_wqh); cudaGetSymbolAddress((void**)&p_wql, g_wql);
    cudaGetSymbolAddress((void**)&p_wph, g_wph); cudaGetSymbolAddress((void**)&p_wpl, g_wpl);
    cudaGetSymbolAddress((void**)&p_ah, g_ah);   cudaGetSymbolAddress((void**)&p_al, g_al);

    cudaFuncSetAttribute(gemm_bf16split_kernel,
                         cudaFuncAttributeMaxDynamicSharedMemorySize, GEMM_SMEM);
    cudaFuncSetAttribute(attn_kernel,
                         cudaFuncAttributeMaxDynamicSharedMemorySize, ATT_SMEM);

    // 0. convert inputs to split-bf16 (weights transposed to [N][K])
    convert_split_kernel<<<(T*HID + 255)/256, 256>>>(x, p_xh, p_xl, T*HID);
    convert_splitT_kernel<<<dim3(THID/32, HID/32), dim3(32, 8)>>>(qkvW, p_wqh, p_wql, HID, THID);
    convert_splitT_kernel<<<dim3(HID/32, HID/32), dim3(32, 8)>>>(projW, p_wph, p_wpl, HID, HID);

    // 1. qkv = x @ Wqkv + b   (mma.sync split-bf16)
    gemm_bf16split_kernel<<<dim3(THID/BN, T/BM), 256, GEMM_SMEM>>>(
        p_xh, p_xl, p_wqh, p_wql, qkvB, p_qkv, T, THID, HID);

    // 2. RoPE + split into per-head Q,K,V
    rope_split_kernel<<<(T*NH*HD + 255)/256, 256>>>(rope);

    // 3. Block-diagonal flash attention (fp32, conflict-free smem)
    attn_kernel<<<dim3(T/64, NH), 256, ATT_SMEM>>>(seg);

    // 4. convert attention output, then out = att @ Wproj + b
    convert_split_kernel<<<(T*HID + 255)/256, 256>>>(p_att, p_ah, p_al, T*HID);
    gemm_bf16split_kernel<<<dim3(HID/BN, T/BM), 256, GEMM_SMEM>>>(
        p_ah, p_al, p_wph, p_wpl, projB, out, T, HID, HID);
}

// round 6
// speedup vs baseline: 2.0070x; 1.0474x over previous
#include <cuda_runtime.h>
#include <cuda_bf16.h>
#include <cstdint>
#include <math.h>

#define T 2048
#define HID 1280
#define NH 16
#define HD 80
#define THID (3*HID)

// ---------------- scratch (static device allocations only) ----------------
__device__ float g_qkv[T*THID];
__device__ float g_q[NH*T*HD];
__device__ float g_k[NH*T*HD];
__device__ float g_v[NH*T*HD];
__device__ float g_att[T*HID];

__device__ __nv_bfloat16 g_xh[T*HID],    g_xl[T*HID];
__device__ __nv_bfloat16 g_wqh[THID*HID], g_wql[THID*HID];
__device__ __nv_bfloat16 g_wph[HID*HID],  g_wpl[HID*HID];
__device__ __nv_bfloat16 g_ah[T*HID],    g_al[T*HID];

// ---------------- helpers ----------------
__device__ __forceinline__ uint32_t smem_to_u32(const void* p) {
    uint32_t a;
    asm("{ .reg .u64 tmp; cvta.to.shared.u64 tmp, %1; cvt.u32.u64 %0, tmp; }"
        : "=r"(a) : "l"(p));
    return a;
}
__device__ __forceinline__ void mma_bf16(float* c, const uint32_t* a, const uint32_t* b) {
    asm volatile("mma.sync.aligned.m16n8k16.row.col.f32.bf16.bf16.f32 "
        "{%0,%1,%2,%3}, {%4,%5,%6,%7}, {%8,%9}, {%0,%1,%2,%3};"
        : "+f"(c[0]), "+f"(c[1]), "+f"(c[2]), "+f"(c[3])
        : "r"(a[0]), "r"(a[1]), "r"(a[2]), "r"(a[3]), "r"(b[0]), "r"(b[1]));
}
__device__ __forceinline__ void ldsm_x4(uint32_t* r, uint32_t addr) {
    asm volatile("ldmatrix.sync.aligned.m8n8.x4.shared.b16 {%0,%1,%2,%3}, [%4];"
        : "=r"(r[0]), "=r"(r[1]), "=r"(r[2]), "=r"(r[3]) : "r"(addr));
}
__device__ __forceinline__ void cp_async16(uint32_t dst, const void* src) {
    asm volatile("cp.async.cg.shared.global [%0], [%1], 16;" :: "r"(dst), "l"(src));
}
#define CP_COMMIT() asm volatile("cp.async.commit_group;" ::: "memory")
#define CP_WAIT1()  asm volatile("cp.async.wait_group 1;" ::: "memory")

// ---------------------------------------------------------------------------
// fp32 -> bf16 hi + bf16 lo split
// ---------------------------------------------------------------------------
__global__ void convert_split_kernel(const float* __restrict__ src,
                                     __nv_bfloat16* __restrict__ h,
                                     __nv_bfloat16* __restrict__ l, int n)
{
    int i = blockIdx.x * blockDim.x + threadIdx.x;
    if (i >= n) return;
    float v = src[i];
    __nv_bfloat16 hh = __float2bfloat16_rn(v);
    h[i] = hh;
    l[i] = __float2bfloat16_rn(v - __bfloat162float(hh));
}

__global__ void convert_splitT_kernel(const float* __restrict__ src,
                                      __nv_bfloat16* __restrict__ h,
                                      __nv_bfloat16* __restrict__ l,
                                      int K, int N)
{
    __shared__ float t[32][33];
    int nb = blockIdx.x * 32, kb = blockIdx.y * 32;
    int tx = threadIdx.x, ty = threadIdx.y;
    #pragma unroll
    for (int j = 0; j < 4; j++)
        t[ty + j * 8][tx] = src[(size_t)(kb + ty + j * 8) * N + nb + tx];
    __syncthreads();
    #pragma unroll
    for (int j = 0; j < 4; j++) {
        float v = t[tx][ty + j * 8];
        __nv_bfloat16 hh = __float2bfloat16_rn(v);
        size_t o = (size_t)(nb + ty + j * 8) * K + kb + tx;
        h[o] = hh;
        l[o] = __float2bfloat16_rn(v - __bfloat162float(hh));
    }
}

// ---------------------------------------------------------------------------
// Split-bf16 tensor-core GEMM via mma.sync (unchanged — proven).
// ---------------------------------------------------------------------------
#define BM 128
#define BN 128
#define BK 32
#define ASTRIDE 40
#define TILE_B (128*ASTRIDE*2)
#define STAGE_B (4*TILE_B)
#define GEMM_SMEM (2*STAGE_B)

__global__ __launch_bounds__(256, 2)
void gemm_bf16split_kernel(const __nv_bfloat16* __restrict__ Ah,
                           const __nv_bfloat16* __restrict__ Al,
                           const __nv_bfloat16* __restrict__ Bh,
                           const __nv_bfloat16* __restrict__ Bl,
                           const float* __restrict__ bias,
                           float* __restrict__ C,
                           int M, int N, int K)
{
    extern __shared__ char sm[];
    const uint32_t sbase = smem_to_u32(sm);

    const int tid  = threadIdx.x;
    const int wid  = tid >> 5;
    const int lane = tid & 31;
    const int m0 = blockIdx.y * BM, n0 = blockIdx.x * BN;
    const int wm = (wid >> 1) * 32;
    const int wn = (wid & 1) * 64;

    float acc[2][8][4];
    #pragma unroll
    for (int a = 0; a < 2; a++)
        #pragma unroll
        for (int b = 0; b < 8; b++)
            #pragma unroll
            for (int c = 0; c < 4; c++) acc[a][b][c] = 0.f;

    const int c_row = tid >> 2;
    const int c_col = (tid & 3) * 8;
    const uint32_t s_off  = (uint32_t)(c_row * ASTRIDE + c_col) * 2;
    const uint32_t s_off2 = s_off + 64 * ASTRIDE * 2;

    const __nv_bfloat16* gAh = Ah + (size_t)(m0 + c_row) * K + c_col;
    const __nv_bfloat16* gAl = Al + (size_t)(m0 + c_row) * K + c_col;
    const __nv_bfloat16* gBh = Bh + (size_t)(n0 + c_row) * K + c_col;
    const __nv_bfloat16* gBl = Bl + (size_t)(n0 + c_row) * K + c_col;
    const size_t g2 = (size_t)64 * K;

    const int niter = K / BK;

    {
        uint32_t sb = sbase;
        cp_async16(sb + s_off,             gAh);
        cp_async16(sb + s_off2,            gAh + g2);
        cp_async16(sb + TILE_B + s_off,    gAl);
        cp_async16(sb + TILE_B + s_off2,   gAl + g2);
        cp_async16(sb + 2*TILE_B + s_off,  gBh);
        cp_async16(sb + 2*TILE_B + s_off2, gBh + g2);
        cp_async16(sb + 3*TILE_B + s_off,  gBl);
        cp_async16(sb + 3*TILE_B + s_off2, gBl + g2);
    }
    CP_COMMIT();

    const int a_row = (lane & 15);
    const int a_colb = ((lane >> 4) << 3) * 2;
    const int b_row = (lane & 7) + ((lane >> 4) << 3);
    const int b_colb = (((lane >> 3) & 1) << 3) * 2;

    for (int it = 0; it < niter; it++) {
        int nk = it + 1;
        if (nk < niter) {
            uint32_t sb = sbase + (nk & 1) * STAGE_B;
            int k0 = nk * BK;
            cp_async16(sb + s_off,             gAh + k0);
            cp_async16(sb + s_off2,            gAh + g2 + k0);
            cp_async16(sb + TILE_B + s_off,    gAl + k0);
            cp_async16(sb + TILE_B + s_off2,   gAl + g2 + k0);
            cp_async16(sb + 2*TILE_B + s_off,  gBh + k0);
            cp_async16(sb + 2*TILE_B + s_off2, gBh + g2 + k0);
            cp_async16(sb + 3*TILE_B + s_off,  gBl + k0);
            cp_async16(sb + 3*TILE_B + s_off2, gBl + g2 + k0);
        }
        CP_COMMIT();
        CP_WAIT1();
        __syncthreads();

        const uint32_t sb = sbase + (it & 1) * STAGE_B;
        const uint32_t sAh = sb;
        const uint32_t sAl = sb + TILE_B;
        const uint32_t sBh = sb + 2*TILE_B;
        const uint32_t sBl = sb + 3*TILE_B;

        #pragma unroll
        for (int k16 = 0; k16 < 2; k16++) {
            const int kcb = k16 * 32;
            uint32_t ah[2][4], al[2][4];
            #pragma unroll
            for (int mi = 0; mi < 2; mi++) {
                uint32_t ro = (uint32_t)(wm + mi*16 + a_row) * (ASTRIDE*2) + kcb + a_colb;
                ldsm_x4(ah[mi], sAh + ro);
                ldsm_x4(al[mi], sAl + ro);
            }
            #pragma unroll
            for (int g = 0; g < 4; g++) {
                uint32_t ro = (uint32_t)(wn + g*16 + b_row) * (ASTRIDE*2) + kcb + b_colb;
                uint32_t bh[4], bl[4];
                ldsm_x4(bh, sBh + ro);
                ldsm_x4(bl, sBl + ro);
                #pragma unroll
                for (int mi = 0; mi < 2; mi++) {
                    mma_bf16(acc[mi][g*2+0], ah[mi], bh + 0);
                    mma_bf16(acc[mi][g*2+0], ah[mi], bl + 0);
                    mma_bf16(acc[mi][g*2+0], al[mi], bh + 0);
                    mma_bf16(acc[mi][g*2+1], ah[mi], bh + 2);
                    mma_bf16(acc[mi][g*2+1], ah[mi], bl + 2);
                    mma_bf16(acc[mi][g*2+1], al[mi], bh + 2);
                }
            }
        }
        __syncthreads();
    }

    #pragma unroll
    for (int mi = 0; mi < 2; mi++) {
        int r0 = m0 + wm + mi*16 + (lane >> 2);
        #pragma unroll
        for (int t = 0; t < 8; t++) {
            int col = n0 + wn + t*8 + (lane & 3)*2;
            float b0 = bias[col], b1 = bias[col + 1];
            float2 v0 = { acc[mi][t][0] + b0, acc[mi][t][1] + b1 };
            float2 v1 = { acc[mi][t][2] + b0, acc[mi][t][3] + b1 };
            *(float2*)(C + (size_t)r0 * N + col)       = v0;
            *(float2*)(C + (size_t)(r0 + 8) * N + col) = v1;
        }
    }
}

// ---------------------------------------------------------------------------
// RoPE + split qkv into per-head [head][T][80] buffers.
// ---------------------------------------------------------------------------
__global__ void rope_split_kernel(const float* __restrict__ rope)
{
    int idx = blockIdx.x * blockDim.x + threadIdx.x;
    if (idx >= T * NH * HD) return;
    int d = idx % HD;
    int n = (idx / HD) % NH;
    int t = idx / (HD * NH);

    int dr = (d < 40) ? d : d - 40;
    float ang = rope[t * 40 + dr];
    float c = cosf(ang), s = sinf(ang);

    const float* qrow = g_qkv + (size_t)t * THID + n * HD;
    float qv, kv;
    if (d < 40) {
        qv = qrow[d] * c        - qrow[d + 40] * s;
        kv = qrow[HID + d] * c  - qrow[HID + d + 40] * s;
    } else {
        qv = qrow[d - 40] * s       + qrow[d] * c;
        kv = qrow[HID + d - 40] * s + qrow[HID + d] * c;
    }
    int o = (n * T + t) * HD + d;
    g_q[o] = qv;
    g_k[o] = kv;
    g_v[o] = qrow[2 * HID + d];
}

// ---------------------------------------------------------------------------
// Flash attention, block-diagonal masking. REWRITTEN (round 6):
//  - lane `sub` owns dims [sub*20, sub*20+20) for Q (registers), K partials,
//    V, and the output accumulator.
//  - Q row held in 20 registers: zero Q smem traffic.
//  - Scores: 20-dim partial dot per lane, shfl_xor(1),(2) reduce ->
//    every lane holds all 32 full scores (no PV broadcasts, no final l reduce).
//  - K/V smem reads are 4-address + 8-way-broadcast: ~64B unique/instr.
//  - Double-buffered K/V tiles, one __syncthreads per tile.
// ---------------------------------------------------------------------------
#define AST 84          // padded row stride (floats); 84 = 21 float4
#define AST4 21

__global__ __launch_bounds__(256)
void attn_kernel(const int* __restrict__ seg)
{
    __shared__ float Ks[2 * 32 * AST];
    __shared__ float Vs[2 * 32 * AST];
    __shared__ int   segk[2 * 32];

    const int n = blockIdx.y;
    const int q0 = blockIdx.x * 64;
    const int tid = threadIdx.x;
    const int row = tid >> 2;      // 0..63
    const int sub = tid & 3;       // 0..3

    // Q row chunk in registers (20 floats = 5 float4)
    float4 q4[5];
    {
        const float4* qsrc = (const float4*)(g_q + (size_t)(n * T + q0 + row) * HD + sub * 20);
        #pragma unroll
        for (int i = 0; i < 5; i++) q4[i] = qsrc[i];
    }

    const int myseg  = seg[q0 + row];
    const int seg_lo = seg[q0];
    const int seg_hi = seg[q0 + 63];

    int lo = 0, hi = T;
    while (lo < hi) { int mid = (lo + hi) >> 1; if (seg[mid] < seg_lo) lo = mid + 1; else hi = mid; }
    const int kstart = lo;
    hi = T;
    while (lo < hi) { int mid = (lo + hi) >> 1; if (seg[mid] <= seg_hi) lo = mid + 1; else hi = mid; }
    const int kend = lo;

    const int kb0 = kstart & ~31;
    const int n_tiles = (kend - kb0 + 31) >> 5;

    // prefetch tile 0 into buffer 0 (float4 granularity; 32*20 float4 per tensor)
    {
        const int kb = kb0;
        float4* Kd = (float4*)Ks;
        float4* Vd = (float4*)Vs;
        for (int i = tid; i < 32 * 20; i += 256) {
            int kk = i / 20, d4 = i % 20;
            int kg = kb + kk;
            float4 kv = {0.f,0.f,0.f,0.f}, vv = {0.f,0.f,0.f,0.f};
            if (kg < kend) {
                const float4* kr = (const float4*)(g_k + (size_t)(n * T + kg) * HD);
                const float4* vr = (const float4*)(g_v + (size_t)(n * T + kg) * HD);
                kv = kr[d4]; vv = vr[d4];
            }
            Kd[kk * AST4 + d4] = kv;
            Vd[kk * AST4 + d4] = vv;
        }
        if (tid < 32) segk[tid] = (kb + tid < T) ? seg[kb + tid] : -1;
    }
    __syncthreads();

    float m = -1e30f, l = 0.f;
    float accv[20];
    #pragma unroll
    for (int i = 0; i < 20; i++) accv[i] = 0.f;
    const float scale = 0.11180339887498949f;   // 1/sqrt(80)

    for (int t = 0; t < n_tiles; t++) {
        const int buf = t & 1;
        const int kb = kb0 + t * 32;

        // prefetch next tile into the other buffer
        if (t + 1 < n_tiles) {
            const int kb2 = kb + 32;
            float4* Kd = (float4*)(Ks + ((t + 1) & 1) * 32 * AST);
            float4* Vd = (float4*)(Vs + ((t + 1) & 1) * 32 * AST);
            for (int i = tid; i < 32 * 20; i += 256) {
                int kk = i / 20, d4 = i % 20;
                int kg = kb2 + kk;
                float4 kv = {0.f,0.f,0.f,0.f}, vv = {0.f,0.f,0.f,0.f};
                if (kg < kend) {
                    const float4* kr = (const float4*)(g_k + (size_t)(n * T + kg) * HD);
                    const float4* vr = (const float4*)(g_v + (size_t)(n * T + kg) * HD);
                    kv = kr[d4]; vv = vr[d4];
                }
                Kd[kk * AST4 + d4] = kv;
                Vd[kk * AST4 + d4] = vv;
            }
            if (tid < 32) segk[((t + 1) & 1) * 32 + tid] = (kb2 + tid < T) ? seg[kb2 + tid] : -1;
        }

        const float4* Kb4 = (const float4*)(Ks + buf * 32 * AST);
        const float4* Vb4 = (const float4*)(Vs + buf * 32 * AST);
        const int*    sg  = segk + buf * 32;

        // Scores for all 32 keys: partial 20-dim dot, then 4-lane reduce.
        float sc[32];
        #pragma unroll
        for (int kk = 0; kk < 32; kk++) {
            const float4* kr = Kb4 + kk * AST4 + sub * 5;
            float s = 0.f;
            #pragma unroll
            for (int i = 0; i < 5; i++) {
                float4 a = q4[i], b = kr[i];
                s += a.x * b.x + a.y * b.y + a.z * b.z + a.w * b.w;
            }
            s += __shfl_xor_sync(0xffffffffu, s, 1);
            s += __shfl_xor_sync(0xffffffffu, s, 2);
            sc[kk] = s * scale;
        }

        // validity mask + tile max
        unsigned vb = 0;
        float cm = -1e30f;
        #pragma unroll
        for (int kk = 0; kk < 32; kk++) {
            int kg = kb + kk;
            bool ok = (kg >= kstart) && (kg < kend) && (sg[kk] == myseg);
            if (ok) { vb |= (1u << kk); cm = fmaxf(cm, sc[kk]); }
        }

        float mnew = fmaxf(m, cm);
        float factor = __expf(m - mnew);
        m = mnew;
        l *= factor;
        #pragma unroll
        for (int i = 0; i < 20; i++) accv[i] *= factor;

        // probs + PV (every lane has all 32 probs; accumulates its 20 dims)
        #pragma unroll
        for (int kk = 0; kk < 32; kk++) {
            float p = (vb & (1u << kk)) ? __expf(sc[kk] - m) : 0.f;
            l += p;
            const float4* vr = Vb4 + kk * AST4 + sub * 5;
            #pragma unroll
            for (int i = 0; i < 5; i++) {
                float4 v = vr[i];
                accv[i*4+0] += p * v.x;
                accv[i*4+1] += p * v.y;
                accv[i*4+2] += p * v.z;
                accv[i*4+3] += p * v.w;
            }
        }
        __syncthreads();
    }

    float inv = 1.f / l;
    float4* o = (float4*)(g_att + (size_t)(q0 + row) * HID + n * HD + sub * 20);
    #pragma unroll
    for (int i = 0; i < 5; i++) {
        float4 v = { accv[i*4+0]*inv, accv[i*4+1]*inv, accv[i*4+2]*inv, accv[i*4+3]*inv };
        o[i] = v;
    }
}

// ---------------------------------------------------------------------------
extern "C" void kernel_launch(void* const* d_in, const int* in_sizes, int n_in,
                              void* d_out, int out_size)
{
    const float* x     = (const float*)d_in[0];
    const float* rope  = (const float*)d_in[1];
    const int*   seg   = (const int*)  d_in[2];
    const float* qkvW  = (const float*)d_in[3];
    const float* qkvB  = (const float*)d_in[4];
    const float* projW = (const float*)d_in[5];
    const float* projB = (const float*)d_in[6];
    float* out = (float*)d_out;

    float *p_qkv, *p_att;
    cudaGetSymbolAddress((void**)&p_qkv, g_qkv);
    cudaGetSymbolAddress((void**)&p_att, g_att);
    __nv_bfloat16 *p_xh, *p_xl, *p_wqh, *p_wql, *p_wph, *p_wpl, *p_ah, *p_al;
    cudaGetSymbolAddress((void**)&p_xh, g_xh);   cudaGetSymbolAddress((void**)&p_xl, g_xl);
    cudaGetSymbolAddress((void**)&p_wqh, g_wqh); cudaGetSymbolAddress((void**)&p_wql, g_wql);
    cudaGetSymbolAddress((void**)&p_wph, g_wph); cudaGetSymbolAddress((void**)&p_wpl, g_wpl);
    cudaGetSymbolAddress((void**)&p_ah, g_ah);   cudaGetSymbolAddress((void**)&p_al, g_al);

    cudaFuncSetAttribute(gemm_bf16split_kernel,
                         cudaFuncAttributeMaxDynamicSharedMemorySize, GEMM_SMEM);

    // 0. convert inputs to split-bf16 (weights transposed to [N][K])
    convert_split_kernel<<<(T*HID + 255)/256, 256>>>(x, p_xh, p_xl, T*HID);
    convert_splitT_kernel<<<dim3(THID/32, HID/32), dim3(32, 8)>>>(qkvW, p_wqh, p_wql, HID, THID);
    convert_splitT_kernel<<<dim3(HID/32, HID/32), dim3(32, 8)>>>(projW, p_wph, p_wpl, HID, HID);

    // 1. qkv = x @ Wqkv + b   (mma.sync split-bf16)
    gemm_bf16split_kernel<<<dim3(THID/BN, T/BM), 256, GEMM_SMEM>>>(
        p_xh, p_xl, p_wqh, p_wql, qkvB, p_qkv, T, THID, HID);

    // 2. RoPE + split into per-head Q,K,V
    rope_split_kernel<<<(T*NH*HD + 255)/256, 256>>>(rope);

    // 3. Block-diagonal flash attention (fp32, register-Q, FFMA-bound)
    attn_kernel<<<dim3(T/64, NH), 256>>>(seg);

    // 4. convert attention output, then out = att @ Wproj + b
    convert_split_kernel<<<(T*HID + 255)/256, 256>>>(p_att, p_ah, p_al, T*HID);
    gemm_bf16split_kernel<<<dim3(HID/BN, T/BM), 256, GEMM_SMEM>>>(
        p_ah, p_al, p_wph, p_wpl, projB, out, T, HID, HID);
}